// round 13
// baseline (speedup 1.0000x reference)
#include <cuda_runtime.h>
#include <cuda_bf16.h>
#include <cstdint>
#include <math.h>

// ---------------------------------------------------------------------------
// Problem constants
// ---------------------------------------------------------------------------
#define K_TOT 8192      // N_T * BS rows
#define D     128
#define NTILE_TOT 2080  // 64*65/2 upper-triangle 128x128 tiles
#define KPOS  24576.0f
#define SCALE_F 1.69864368f   // sqrt(2 * log2(e));  acc = log2e * sim
#define LN2F   0.693147181f

// Smem layout (bytes)
#define SM_A    0              // 128 rows x 256B = 32KB
#define SM_B0   32768
#define SM_B1   65536
#define SM_ROW  98304          // 128 x 2 floats
#define SM_COL  99328          // 128 x 4 floats
#define SM_TOTAL 101376

// Scratch
__device__ __align__(16) __nv_bfloat16 g_snb[K_TOT * D];
__device__ float g_Srow[NTILE_TOT * 128];
__device__ float g_Scol[NTILE_TOT * 128];
__device__ float g_pos[K_TOT * 4];
__device__ float g_part[32];
__device__ int   g_sem;        // self-resetting last-block semaphore

// ---------------------------------------------------------------------------
// PTX helpers
// ---------------------------------------------------------------------------
__device__ __forceinline__ float ex2f(float x) {
    float r; asm("ex2.approx.f32 %0, %1;" : "=f"(r) : "f"(x)); return r;
}

#define CP16(dst, src) \
    asm volatile("cp.async.cg.shared.global [%0], [%1], 16;\n" :: "r"(dst), "l"(src))
#define CPCOMMIT() asm volatile("cp.async.commit_group;\n")
#define CPWAIT1()  asm volatile("cp.async.wait_group 1;\n")
#define CPWAIT0()  asm volatile("cp.async.wait_group 0;\n")

#define LDSM4(R0,R1,R2,R3,ADDR) \
    asm volatile("ldmatrix.sync.aligned.m8n8.x4.shared.b16 {%0,%1,%2,%3}, [%4];\n" \
        : "=r"(R0),"=r"(R1),"=r"(R2),"=r"(R3) : "r"(ADDR))

#define MMA16816(D0,D1,D2,D3,A0,A1,A2,A3,B0,B1) \
    asm volatile("mma.sync.aligned.m16n8k16.row.col.f32.bf16.bf16.f32 " \
        "{%0,%1,%2,%3}, {%4,%5,%6,%7}, {%8,%9}, {%0,%1,%2,%3};\n" \
        : "+f"(D0),"+f"(D1),"+f"(D2),"+f"(D3) \
        : "r"(A0),"r"(A1),"r"(A2),"r"(A3),"r"(B0),"r"(B1))

__device__ __forceinline__ int tile_I(int k, int tt) {
    return (tt < 64 - k) ? k : (63 - k);
}
__device__ __forceinline__ int tile_J(int k, int tt) {
    return (tt < 64 - k) ? (k + tt) : ((63 - k) + (tt - (64 - k)));
}

// ---------------------------------------------------------------------------
// Kernel 1: row L2-normalize, pre-scale by sqrt(2*log2e), emit bf16.
// ---------------------------------------------------------------------------
__global__ void normalize_kernel(const float* __restrict__ z) {
    int gw = (blockIdx.x * blockDim.x + threadIdx.x) >> 5;
    int lane = threadIdx.x & 31;
    float4 v = ((const float4*)(z + (size_t)gw * D))[lane];
    float ss = v.x*v.x + v.y*v.y + v.z*v.z + v.w*v.w;
    #pragma unroll
    for (int off = 16; off; off >>= 1)
        ss += __shfl_xor_sync(0xffffffffu, ss, off);
    float inv = SCALE_F / fmaxf(sqrtf(ss), 1e-8f);
    __nv_bfloat162 p0 = __floats2bfloat162_rn(v.x * inv, v.y * inv);
    __nv_bfloat162 p1 = __floats2bfloat162_rn(v.z * inv, v.w * inv);
    uint2 o;
    o.x = *(unsigned int*)&p0;
    o.y = *(unsigned int*)&p1;
    *(uint2*)(g_snb + (size_t)gw * D + lane * 4) = o;
}

// ---------------------------------------------------------------------------
// 128-row x 128-k bf16 tile loader (32KB), 16B-chunk XOR swizzle. 256 threads.
// ---------------------------------------------------------------------------
__device__ __forceinline__ void load_tile(uint32_t dstbase,
                                          const __nv_bfloat16* src, int t) {
    #pragma unroll
    for (int it = 0; it < 8; ++it) {
        int f = t + 256 * it;          // 0..2047
        int j = f >> 4, c = f & 15;
        uint32_t dst = dstbase + j * 256 + ((c ^ (j & 7)) << 4);
        CP16(dst, (const char*)src + j * 256 + c * 16);
    }
}

// ---------------------------------------------------------------------------
// One tile's MMA (into accC) with the ex2 row/col accumulation of the
// PREVIOUS tile (accP) interleaved into the k-loop (tensor-pipe shadow).
// Also handles per-tile wait/A-reload/sync. Zeroes Ssum/colacc on entry.
// ---------------------------------------------------------------------------
template<bool DOEPI>
__device__ __forceinline__ void mma_tile(
    int lt, int lastLt, int k, int& curI, bool& needA,
    uint32_t sb, int t, int lane, int wr, int wc,
    uint32_t (&af)[2][8][4],
    float (&accC)[2][8][4], float (&accP)[2][8][4],
    float (&Ssum)[4], float (&colacc)[16])
{
    const int I = tile_I(k, lt);
    if (lt == lastLt) { CPWAIT0(); } else { CPWAIT1(); }
    if (I != curI) {                       // at most once per CTA
        load_tile(sb + SM_A, g_snb + (size_t)I * 128 * D, t);
        CPCOMMIT(); CPWAIT0();
        curI = I; needA = true;
    }
    __syncthreads();
    if (needA) {
        #pragma unroll
        for (int mt = 0; mt < 2; ++mt) {
            int row = wr * 32 + mt * 16 + (lane & 15);
            uint32_t rbase = sb + SM_A + row * 256;
            #pragma unroll
            for (int ks = 0; ks < 8; ++ks) {
                uint32_t addr = rbase + (((ks * 2 + (lane >> 4)) ^ (row & 7)) << 4);
                LDSM4(af[mt][ks][0], af[mt][ks][1], af[mt][ks][2], af[mt][ks][3], addr);
            }
        }
        needA = false;
    }

    #pragma unroll
    for (int s4 = 0; s4 < 4; ++s4) Ssum[s4] = 0.f;
    #pragma unroll
    for (int c16 = 0; c16 < 16; ++c16) colacc[c16] = 0.f;

    const uint32_t Bb = sb + ((lt & 1) ? SM_B1 : SM_B0);
    #pragma unroll
    for (int mt = 0; mt < 2; ++mt)
        #pragma unroll
        for (int nt = 0; nt < 8; ++nt)
            #pragma unroll
            for (int e = 0; e < 4; ++e) accC[mt][nt][e] = 0.f;

    #pragma unroll
    for (int ks = 0; ks < 8; ++ks) {
        #pragma unroll
        for (int ntp = 0; ntp < 4; ++ntp) {
            int colr = wc * 64 + ntp * 16 + (lane & 15);
            uint32_t addr = Bb + colr * 256 +
                            (((ks * 2 + (lane >> 4)) ^ (colr & 7)) << 4);
            uint32_t b0, b1, b2, b3;
            LDSM4(b0, b1, b2, b3, addr);
            MMA16816(accC[0][2*ntp][0], accC[0][2*ntp][1], accC[0][2*ntp][2], accC[0][2*ntp][3],
                     af[0][ks][0], af[0][ks][1], af[0][ks][2], af[0][ks][3], b0, b2);
            MMA16816(accC[1][2*ntp][0], accC[1][2*ntp][1], accC[1][2*ntp][2], accC[1][2*ntp][3],
                     af[1][ks][0], af[1][ks][1], af[1][ks][2], af[1][ks][3], b0, b2);
            MMA16816(accC[0][2*ntp+1][0], accC[0][2*ntp+1][1], accC[0][2*ntp+1][2], accC[0][2*ntp+1][3],
                     af[0][ks][0], af[0][ks][1], af[0][ks][2], af[0][ks][3], b1, b3);
            MMA16816(accC[1][2*ntp+1][0], accC[1][2*ntp+1][1], accC[1][2*ntp+1][2], accC[1][2*ntp+1][3],
                     af[1][ks][0], af[1][ks][1], af[1][ks][2], af[1][ks][3], b1, b3);
        }
        if (DOEPI) {
            #pragma unroll
            for (int q = 0; q < 8; ++q) {
                int f = ks * 8 + q;                // 0..63
                int mt = f >> 5, nt = (f >> 2) & 7, e = f & 3;
                float x = ex2f(accP[mt][nt][e]);
                Ssum[mt*2 + (e >> 1)] += x;
                colacc[nt*2 + (e & 1)] += x;
            }
        }
    }
}

// ---------------------------------------------------------------------------
// Finish tile lt (whose acc is accP and whose ex2 sums are in Ssum/colacc):
// collision fixup, reductions, staging, global partial writes.
// ---------------------------------------------------------------------------
__device__ __forceinline__ void finish_tile(
    int lt, int k, int t, int lane, int wr, int wc,
    float* sRow, float* sCol,
    float (&accP)[2][8][4], float (&Ssum)[4], float (&colacc)[16])
{
    const int I = tile_I(k, lt), J = tile_J(k, lt);

    // collisions (j == i mod 2048) iff (J-I)%16==0, at local row==col
    if (((J - I) & 15) == 0) {
        #pragma unroll
        for (int mt = 0; mt < 2; ++mt)
            #pragma unroll
            for (int nt = 0; nt < 8; ++nt)
                #pragma unroll
                for (int e = 0; e < 4; ++e) {
                    int rl = wr*32 + mt*16 + (lane >> 2) + ((e >> 1) << 3);
                    int cl = wc*64 + nt*8 + ((lane & 3) << 1) + (e & 1);
                    if (rl == cl) {
                        float v = accP[mt][nt][e];
                        float x = ex2f(v);
                        Ssum[mt*2 + (e >> 1)] -= x;
                        colacc[nt*2 + (e & 1)] -= x;
                        if (I != J) {           // positive pair, both directions
                            int gi = I*128 + rl, gj = J*128 + cl;
                            g_pos[gi*4 + (J >> 4)] = v;
                            g_pos[gj*4 + (I >> 4)] = v;
                        }
                    }
                }
    }

    // row partials: quad-reduce, stage [128][2]
    #pragma unroll
    for (int s4 = 0; s4 < 4; ++s4) {
        Ssum[s4] += __shfl_xor_sync(0xffffffffu, Ssum[s4], 1);
        Ssum[s4] += __shfl_xor_sync(0xffffffffu, Ssum[s4], 2);
    }
    if ((lane & 3) == 0) {
        #pragma unroll
        for (int s4 = 0; s4 < 4; ++s4) {
            int lrow = wr*32 + (s4 >> 1)*16 + (lane >> 2) + (s4 & 1)*8;
            sRow[lrow*2 + wc] = Ssum[s4];
        }
    }
    // col partials: reduce over lanes sharing lane&3, stage [128][4]
    #pragma unroll
    for (int c16 = 0; c16 < 16; ++c16) {
        colacc[c16] += __shfl_xor_sync(0xffffffffu, colacc[c16], 4);
        colacc[c16] += __shfl_xor_sync(0xffffffffu, colacc[c16], 8);
        colacc[c16] += __shfl_xor_sync(0xffffffffu, colacc[c16], 16);
    }
    if (lane < 4) {
        #pragma unroll
        for (int c16 = 0; c16 < 16; ++c16) {
            int cl = wc*64 + (c16 >> 1)*8 + lane*2 + (c16 & 1);
            sCol[cl*4 + wr] = colacc[c16];
        }
    }
    __syncthreads();    // staging done; also proves all warps past this tile's MMA

    const int tid = I*64 - (I*(I - 1))/2 + (J - I);
    if (t < 128) {
        g_Srow[tid*128 + t] = sRow[t*2] + sRow[t*2 + 1];
    } else {
        int r = t - 128;
        g_Scol[tid*128 + r] = sCol[r*4] + sCol[r*4+1] + sCol[r*4+2] + sCol[r*4+3];
    }
}

// Tail: un-deferred epilogue for the last tile.
__device__ __forceinline__ void tail_epi(
    int lt, int k, int t, int lane, int wr, int wc,
    float* sRow, float* sCol,
    float (&accP)[2][8][4], float (&Ssum)[4], float (&colacc)[16])
{
    #pragma unroll
    for (int s4 = 0; s4 < 4; ++s4) Ssum[s4] = 0.f;
    #pragma unroll
    for (int c16 = 0; c16 < 16; ++c16) colacc[c16] = 0.f;
    #pragma unroll
    for (int mt = 0; mt < 2; ++mt)
        #pragma unroll
        for (int nt = 0; nt < 8; ++nt)
            #pragma unroll
            for (int e = 0; e < 4; ++e) {
                float x = ex2f(accP[mt][nt][e]);
                Ssum[mt*2 + (e >> 1)] += x;
                colacc[nt*2 + (e & 1)] += x;
            }
    finish_tile(lt, k, t, lane, wr, wc, sRow, sCol, accP, Ssum, colacc);
}

// ---------------------------------------------------------------------------
// Kernel 2: symmetric HMMA simmat, deferred (pipelined) exp2 epilogue.
// 128 CTAs x 256 threads; warp grid 4x2 (wr 32-row, wc 64-col).
// ---------------------------------------------------------------------------
__global__ void __launch_bounds__(256, 1) clblock_mma_kernel() {
    extern __shared__ char smem[];
    float* sRow = (float*)(smem + SM_ROW);
    float* sCol = (float*)(smem + SM_COL);

    const int t = threadIdx.x, lane = t & 31, w = t >> 5;
    const int wr = w >> 1, wc = w & 1;
    const int k = blockIdx.x >> 2, s = blockIdx.x & 3;
    const int s0 = s ? (17 + 16 * (s - 1)) : 0;
    const int lastLt = s0 + (s ? 16 : 17) - 1;
    uint32_t sb = (uint32_t)__cvta_generic_to_shared(smem);

    // ---- prologue: A(I0), B(s0), B(s0+1) ----
    int curI = tile_I(k, s0);
    load_tile(sb + SM_A, g_snb + (size_t)curI * 128 * D, t);
    load_tile(sb + ((s0 & 1) ? SM_B1 : SM_B0),
              g_snb + (size_t)tile_J(k, s0) * 128 * D, t);
    CPCOMMIT();
    load_tile(sb + (((s0 + 1) & 1) ? SM_B1 : SM_B0),
              g_snb + (size_t)tile_J(k, s0 + 1) * 128 * D, t);
    CPCOMMIT();
    bool needA = true;
    uint32_t af[2][8][4];
    float accA[2][8][4], accB[2][8][4];
    float Ssum[4], colacc[16];

    // ---- peel tile s0 (no previous epilogue) ----
    mma_tile<false>(s0, lastLt, k, curI, needA, sb, t, lane, wr, wc,
                    af, accA, accB, Ssum, colacc);
    __syncthreads();                       // all warps done MMA(s0)
    if (s0 + 2 <= lastLt) {
        load_tile(sb + (s0 & 1 ? SM_B1 : SM_B0),
                  g_snb + (size_t)tile_J(k, s0 + 2) * 128 * D, t);
        CPCOMMIT();
    }

    int m = s0 + 1;
    for (; m + 1 <= lastLt; m += 2) {
        mma_tile<true>(m, lastLt, k, curI, needA, sb, t, lane, wr, wc,
                       af, accB, accA, Ssum, colacc);
        finish_tile(m - 1, k, t, lane, wr, wc, sRow, sCol, accA, Ssum, colacc);
        if (m + 2 <= lastLt) {
            load_tile(sb + (m & 1 ? SM_B1 : SM_B0),
                      g_snb + (size_t)tile_J(k, m + 2) * 128 * D, t);
            CPCOMMIT();
        }
        mma_tile<true>(m + 1, lastLt, k, curI, needA, sb, t, lane, wr, wc,
                       af, accA, accB, Ssum, colacc);
        finish_tile(m, k, t, lane, wr, wc, sRow, sCol, accB, Ssum, colacc);
        if (m + 3 <= lastLt) {
            load_tile(sb + ((m + 1) & 1 ? SM_B1 : SM_B0),
                      g_snb + (size_t)tile_J(k, m + 3) * 128 * D, t);
            CPCOMMIT();
        }
    }

    if (m == lastLt) {                     // even tile count: one leftover
        mma_tile<true>(m, lastLt, k, curI, needA, sb, t, lane, wr, wc,
                       af, accB, accA, Ssum, colacc);
        finish_tile(m - 1, k, t, lane, wr, wc, sRow, sCol, accA, Ssum, colacc);
        __syncthreads();
        tail_epi(lastLt, k, t, lane, wr, wc, sRow, sCol, accB, Ssum, colacc);
    } else {                               // odd tile count: last tile in accA
        __syncthreads();
        tail_epi(lastLt, k, t, lane, wr, wc, sRow, sCol, accA, Ssum, colacc);
    }
}

// ---------------------------------------------------------------------------
// Kernel 3: per-row S0 gather + loss, fused final reduction (last block).
// ---------------------------------------------------------------------------
__global__ void rowloss_kernel(float* __restrict__ out) {
    __shared__ float sh[8];
    __shared__ int slast;
    int i = blockIdx.x * 256 + threadIdx.x;
    int I = i >> 7, r = i & 127;
    float S0 = 0.f;
    int b = I*64 - (I*(I - 1))/2;
    for (int J = I; J < 64; ++J)
        S0 += g_Srow[(b + J - I)*128 + r];
    for (int Ip = 0; Ip < I; ++Ip) {
        int b2 = Ip*64 - (Ip*(Ip - 1))/2;
        S0 += g_Scol[(b2 + I - Ip)*128 + r];
    }
    int myq = i >> 11;
    float c = 0.f;
    #pragma unroll
    for (int qq = 0; qq < 4; ++qq) {
        if (qq != myq) {
            float ap = g_pos[i*4 + qq];          // = log2e * sim_pos
            c += logf(exp2f(ap) + S0) - ap * LN2F;
        }
    }
    #pragma unroll
    for (int off = 16; off; off >>= 1)
        c += __shfl_xor_sync(0xffffffffu, c, off);
    if ((threadIdx.x & 31) == 0) sh[threadIdx.x >> 5] = c;
    __syncthreads();
    if (threadIdx.x == 0) {
        float ss = 0.f;
        #pragma unroll
        for (int q = 0; q < 8; ++q) ss += sh[q];
        g_part[blockIdx.x] = ss;
        __threadfence();
        int v = atomicAdd(&g_sem, 1);
        slast = (v == 31) ? 1 : 0;
    }
    __syncthreads();
    if (slast && threadIdx.x < 32) {
        float v2 = g_part[threadIdx.x];
        #pragma unroll
        for (int off = 16; off; off >>= 1)
            v2 += __shfl_xor_sync(0xffffffffu, v2, off);
        if (threadIdx.x == 0) {
            out[0] = v2 / KPOS;
            g_sem = 0;                     // reset for next graph replay
        }
    }
}

// ---------------------------------------------------------------------------
extern "C" void kernel_launch(void* const* d_in, const int* in_sizes, int n_in,
                              void* d_out, int out_size) {
    const float* z = (const float*)d_in[0];
    float* out = (float*)d_out;

    cudaFuncSetAttribute(clblock_mma_kernel,
                         cudaFuncAttributeMaxDynamicSharedMemorySize, SM_TOTAL);

    normalize_kernel<<<K_TOT / 8, 256>>>(z);
    clblock_mma_kernel<<<128, 256, SM_TOTAL>>>();
    rowloss_kernel<<<32, 256>>>(out);
}

// round 14
// speedup vs baseline: 1.0579x; 1.0579x over previous
#include <cuda_runtime.h>
#include <cuda_bf16.h>
#include <cstdint>
#include <math.h>

// ---------------------------------------------------------------------------
// Problem constants
// ---------------------------------------------------------------------------
#define K_TOT 8192      // N_T * BS rows
#define D     128
#define NTILE_TOT 2080  // 64*65/2 upper-triangle 128x128 tiles
#define KPOS  24576.0f
#define SCALE_F 1.69864368f   // sqrt(2 * log2(e));  acc = log2e * sim
#define LN2F   0.693147181f

// Smem layout (bytes)
#define SM_A    0              // 128 rows x 256B = 32KB
#define SM_B0   32768
#define SM_B1   65536
#define SM_ROW  98304          // 128 x 2 floats
#define SM_COL  99328          // 128 x 4 floats
#define SM_TOTAL 101376

// Scratch
__device__ __align__(16) __nv_bfloat16 g_snb[K_TOT * D];
__device__ float g_Srow[NTILE_TOT * 128];
__device__ float g_Scol[NTILE_TOT * 128];
__device__ float g_pos[K_TOT * 4];
__device__ float g_part[32];
__device__ int   g_sem;        // self-resetting last-block semaphore

// ---------------------------------------------------------------------------
// PTX helpers
// ---------------------------------------------------------------------------
__device__ __forceinline__ float ex2f(float x) {
    float r; asm("ex2.approx.f32 %0, %1;" : "=f"(r) : "f"(x)); return r;
}

#define CP16(dst, src) \
    asm volatile("cp.async.cg.shared.global [%0], [%1], 16;\n" :: "r"(dst), "l"(src))
#define CPCOMMIT() asm volatile("cp.async.commit_group;\n")
#define CPWAIT1()  asm volatile("cp.async.wait_group 1;\n")
#define CPWAIT0()  asm volatile("cp.async.wait_group 0;\n")

#define LDSM4(R0,R1,R2,R3,ADDR) \
    asm volatile("ldmatrix.sync.aligned.m8n8.x4.shared.b16 {%0,%1,%2,%3}, [%4];\n" \
        : "=r"(R0),"=r"(R1),"=r"(R2),"=r"(R3) : "r"(ADDR))

#define MMA16816(D0,D1,D2,D3,A0,A1,A2,A3,B0,B1) \
    asm volatile("mma.sync.aligned.m16n8k16.row.col.f32.bf16.bf16.f32 " \
        "{%0,%1,%2,%3}, {%4,%5,%6,%7}, {%8,%9}, {%0,%1,%2,%3};\n" \
        : "+f"(D0),"+f"(D1),"+f"(D2),"+f"(D3) \
        : "r"(A0),"r"(A1),"r"(A2),"r"(A3),"r"(B0),"r"(B1))

// ---------------------------------------------------------------------------
// Kernel 1: row L2-normalize, pre-scale by sqrt(2*log2e), emit bf16.
// ---------------------------------------------------------------------------
__global__ void normalize_kernel(const float* __restrict__ z) {
    int gw = (blockIdx.x * blockDim.x + threadIdx.x) >> 5;
    int lane = threadIdx.x & 31;
    float4 v = ((const float4*)(z + (size_t)gw * D))[lane];
    float ss = v.x*v.x + v.y*v.y + v.z*v.z + v.w*v.w;
    #pragma unroll
    for (int off = 16; off; off >>= 1)
        ss += __shfl_xor_sync(0xffffffffu, ss, off);
    float inv = SCALE_F / fmaxf(sqrtf(ss), 1e-8f);
    __nv_bfloat162 p0 = __floats2bfloat162_rn(v.x * inv, v.y * inv);
    __nv_bfloat162 p1 = __floats2bfloat162_rn(v.z * inv, v.w * inv);
    uint2 o;
    o.x = *(unsigned int*)&p0;
    o.y = *(unsigned int*)&p1;
    *(uint2*)(g_snb + (size_t)gw * D + lane * 4) = o;
}

// ---------------------------------------------------------------------------
// 128-row x 128-k bf16 tile loader (32KB), 16B-chunk XOR swizzle. 256 threads.
// ---------------------------------------------------------------------------
__device__ __forceinline__ void load_tile(uint32_t dstbase,
                                          const __nv_bfloat16* src, int t) {
    #pragma unroll
    for (int it = 0; it < 8; ++it) {
        int f = t + 256 * it;          // 0..2047
        int j = f >> 4, c = f & 15;
        uint32_t dst = dstbase + j * 256 + ((c ^ (j & 7)) << 4);
        CP16(dst, (const char*)src + j * 256 + c * 16);
    }
}

// ---------------------------------------------------------------------------
// Kernel 2: symmetric (upper-triangle) HMMA simmat + exp2 row/col sums.
// 128 CTAs x 256 threads. CTA (k = b>>2, s = b&3) handles a 16/17-tile
// segment of chain k = [rows k sweep J=k..63] + [rows 63-k sweep].
// Warp grid 4x2: wr = w>>1 (32-row group), wc = w&1 (64-col half).
// ---------------------------------------------------------------------------
__global__ void __launch_bounds__(256, 1) clblock_mma_kernel() {
    extern __shared__ char smem[];
    float* sRow = (float*)(smem + SM_ROW);   // [128][2]
    float* sCol = (float*)(smem + SM_COL);   // [128][4]

    const int t = threadIdx.x, lane = t & 31, w = t >> 5;
    const int wr = w >> 1, wc = w & 1;
    const int k = blockIdx.x >> 2, s = blockIdx.x & 3;
    const int s0 = s ? (17 + 16 * (s - 1)) : 0;
    const int lastLt = s0 + (s ? 16 : 17) - 1;
    uint32_t sb = (uint32_t)__cvta_generic_to_shared(smem);

    #define TILE_I(tt) (((tt) < 64 - k) ? k : (63 - k))
    #define TILE_J(tt) (((tt) < 64 - k) ? (k + (tt)) : ((63 - k) + ((tt) - (64 - k))))

    // ---- prologue: A(I0), B(s0), B(s0+1) ----
    int curI = TILE_I(s0);
    load_tile(sb + SM_A, g_snb + (size_t)curI * 128 * D, t);
    load_tile(sb + ((s0 & 1) ? SM_B1 : SM_B0),
              g_snb + (size_t)TILE_J(s0) * 128 * D, t);
    CPCOMMIT();
    if (s0 + 1 <= lastLt) {
        load_tile(sb + (((s0 + 1) & 1) ? SM_B1 : SM_B0),
                  g_snb + (size_t)TILE_J(s0 + 1) * 128 * D, t);
        CPCOMMIT();
    }
    bool needA = true;
    uint32_t af[2][8][4];

    for (int lt = s0; lt <= lastLt; ++lt) {
        const int I = TILE_I(lt), J = TILE_J(lt);
        if (lt == lastLt) { CPWAIT0(); } else { CPWAIT1(); }
        if (I != curI) {                       // at most once per CTA
            load_tile(sb + SM_A, g_snb + (size_t)I * 128 * D, t);
            CPCOMMIT(); CPWAIT0();
            curI = I; needA = true;
        }
        __syncthreads();
        if (needA) {                           // (re)load A fragments
            #pragma unroll
            for (int mt = 0; mt < 2; ++mt) {
                int row = wr * 32 + mt * 16 + (lane & 15);
                uint32_t rbase = sb + SM_A + row * 256;
                #pragma unroll
                for (int ks = 0; ks < 8; ++ks) {
                    uint32_t addr = rbase + (((ks * 2 + (lane >> 4)) ^ (row & 7)) << 4);
                    LDSM4(af[mt][ks][0], af[mt][ks][1], af[mt][ks][2], af[mt][ks][3], addr);
                }
            }
            needA = false;
        }

        const uint32_t Bb = sb + ((lt & 1) ? SM_B1 : SM_B0);
        float acc[2][8][4];
        #pragma unroll
        for (int mt = 0; mt < 2; ++mt)
            #pragma unroll
            for (int nt = 0; nt < 8; ++nt)
                #pragma unroll
                for (int e = 0; e < 4; ++e) acc[mt][nt][e] = 0.f;

        #pragma unroll
        for (int ks = 0; ks < 8; ++ks) {
            #pragma unroll
            for (int ntp = 0; ntp < 4; ++ntp) {
                int colr = wc * 64 + ntp * 16 + (lane & 15);
                uint32_t addr = Bb + colr * 256 +
                                (((ks * 2 + (lane >> 4)) ^ (colr & 7)) << 4);
                uint32_t b0, b1, b2, b3;
                LDSM4(b0, b1, b2, b3, addr);
                MMA16816(acc[0][2*ntp][0], acc[0][2*ntp][1], acc[0][2*ntp][2], acc[0][2*ntp][3],
                         af[0][ks][0], af[0][ks][1], af[0][ks][2], af[0][ks][3], b0, b2);
                MMA16816(acc[1][2*ntp][0], acc[1][2*ntp][1], acc[1][2*ntp][2], acc[1][2*ntp][3],
                         af[1][ks][0], af[1][ks][1], af[1][ks][2], af[1][ks][3], b0, b2);
                MMA16816(acc[0][2*ntp+1][0], acc[0][2*ntp+1][1], acc[0][2*ntp+1][2], acc[0][2*ntp+1][3],
                         af[0][ks][0], af[0][ks][1], af[0][ks][2], af[0][ks][3], b1, b3);
                MMA16816(acc[1][2*ntp+1][0], acc[1][2*ntp+1][1], acc[1][2*ntp+1][2], acc[1][2*ntp+1][3],
                         af[1][ks][0], af[1][ks][1], af[1][ks][2], af[1][ks][3], b1, b3);
            }
        }

        // ---- epilogue: ex2 once per element -> row sums AND col sums ----
        float Ssum[4] = {0.f, 0.f, 0.f, 0.f};
        float colacc[16];
        #pragma unroll
        for (int c16 = 0; c16 < 16; ++c16) colacc[c16] = 0.f;
        #pragma unroll
        for (int mt = 0; mt < 2; ++mt)
            #pragma unroll
            for (int nt = 0; nt < 8; ++nt)
                #pragma unroll
                for (int e = 0; e < 4; ++e) {
                    float x = ex2f(acc[mt][nt][e]);
                    Ssum[mt*2 + (e >> 1)] += x;
                    colacc[nt*2 + (e & 1)] += x;
                }

        // collisions (j == i mod 2048) iff (J-I)%16==0, at local row==col
        if (((J - I) & 15) == 0) {
            #pragma unroll
            for (int mt = 0; mt < 2; ++mt)
                #pragma unroll
                for (int nt = 0; nt < 8; ++nt)
                    #pragma unroll
                    for (int e = 0; e < 4; ++e) {
                        int rl = wr*32 + mt*16 + (lane >> 2) + ((e >> 1) << 3);
                        int cl = wc*64 + nt*8 + ((lane & 3) << 1) + (e & 1);
                        if (rl == cl) {
                            float v = acc[mt][nt][e];
                            float x = ex2f(v);
                            Ssum[mt*2 + (e >> 1)] -= x;
                            colacc[nt*2 + (e & 1)] -= x;
                            if (I != J) {       // positive pair, both directions
                                int gi = I*128 + rl, gj = J*128 + cl;
                                g_pos[gi*4 + (J >> 4)] = v;
                                g_pos[gj*4 + (I >> 4)] = v;
                            }
                        }
                    }
        }

        // ---- row partials: quad-reduce, stage [128][2] ----
        #pragma unroll
        for (int s4 = 0; s4 < 4; ++s4) {
            Ssum[s4] += __shfl_xor_sync(0xffffffffu, Ssum[s4], 1);
            Ssum[s4] += __shfl_xor_sync(0xffffffffu, Ssum[s4], 2);
        }
        if ((lane & 3) == 0) {
            #pragma unroll
            for (int s4 = 0; s4 < 4; ++s4) {
                int lrow = wr*32 + (s4 >> 1)*16 + (lane >> 2) + (s4 & 1)*8;
                sRow[lrow*2 + wc] = Ssum[s4];
            }
        }
        // ---- col partials: reduce over lanes sharing lane&3, stage [128][4] ----
        #pragma unroll
        for (int c16 = 0; c16 < 16; ++c16) {
            colacc[c16] += __shfl_xor_sync(0xffffffffu, colacc[c16], 4);
            colacc[c16] += __shfl_xor_sync(0xffffffffu, colacc[c16], 8);
            colacc[c16] += __shfl_xor_sync(0xffffffffu, colacc[c16], 16);
        }
        if (lane < 4) {
            #pragma unroll
            for (int c16 = 0; c16 < 16; ++c16) {
                int cl = wc*64 + (c16 >> 1)*8 + lane*2 + (c16 & 1);
                sCol[cl*4 + wr] = colacc[c16];
            }
        }
        __syncthreads();    // staging done; B buffer free

        const int tid = I*64 - (I*(I - 1))/2 + (J - I);
        if (t < 128) {
            g_Srow[tid*128 + t] = sRow[t*2] + sRow[t*2 + 1];
        } else {
            int r = t - 128;
            g_Scol[tid*128 + r] = sCol[r*4] + sCol[r*4+1] + sCol[r*4+2] + sCol[r*4+3];
        }

        if (lt + 2 <= lastLt) {
            load_tile(sb + ((lt & 1) ? SM_B1 : SM_B0),
                      g_snb + (size_t)TILE_J(lt + 2) * 128 * D, t);
            CPCOMMIT();
        }
    }
    #undef TILE_I
    #undef TILE_J
}

// ---------------------------------------------------------------------------
// Kernel 3: per-row S0 gather + loss, fused final reduction (last block).
// ---------------------------------------------------------------------------
__global__ void rowloss_kernel(float* __restrict__ out) {
    __shared__ float sh[8];
    __shared__ int slast;
    int i = blockIdx.x * 256 + threadIdx.x;
    int I = i >> 7, r = i & 127;
    float S0 = 0.f;
    int b = I*64 - (I*(I - 1))/2;
    for (int J = I; J < 64; ++J)
        S0 += g_Srow[(b + J - I)*128 + r];
    for (int Ip = 0; Ip < I; ++Ip) {
        int b2 = Ip*64 - (Ip*(Ip - 1))/2;
        S0 += g_Scol[(b2 + I - Ip)*128 + r];
    }
    int myq = i >> 11;
    float c = 0.f;
    #pragma unroll
    for (int qq = 0; qq < 4; ++qq) {
        if (qq != myq) {
            float ap = g_pos[i*4 + qq];          // = log2e * sim_pos
            c += logf(exp2f(ap) + S0) - ap * LN2F;
        }
    }
    #pragma unroll
    for (int off = 16; off; off >>= 1)
        c += __shfl_xor_sync(0xffffffffu, c, off);
    if ((threadIdx.x & 31) == 0) sh[threadIdx.x >> 5] = c;
    __syncthreads();
    if (threadIdx.x == 0) {
        float ss = 0.f;
        #pragma unroll
        for (int q = 0; q < 8; ++q) ss += sh[q];
        g_part[blockIdx.x] = ss;
        __threadfence();
        int v = atomicAdd(&g_sem, 1);
        slast = (v == 31) ? 1 : 0;
    }
    __syncthreads();
    if (slast && threadIdx.x < 32) {
        float v2 = g_part[threadIdx.x];
        #pragma unroll
        for (int off = 16; off; off >>= 1)
            v2 += __shfl_xor_sync(0xffffffffu, v2, off);
        if (threadIdx.x == 0) {
            out[0] = v2 / KPOS;
            g_sem = 0;                     // reset for next graph replay
        }
    }
}

// ---------------------------------------------------------------------------
extern "C" void kernel_launch(void* const* d_in, const int* in_sizes, int n_in,
                              void* d_out, int out_size) {
    const float* z = (const float*)d_in[0];
    float* out = (float*)d_out;

    cudaFuncSetAttribute(clblock_mma_kernel,
                         cudaFuncAttributeMaxDynamicSharedMemorySize, SM_TOTAL);

    normalize_kernel<<<K_TOT / 8, 256>>>(z);
    clblock_mma_kernel<<<128, 256, SM_TOTAL>>>();
    rowloss_kernel<<<32, 256>>>(out);
}